// round 15
// baseline (speedup 1.0000x reference)
#include <cuda_runtime.h>
#include <cuda_fp16.h>
#include <math.h>
#include <cstdint>

#define NN   50000
#define EE   800000
#define DINF 146
#define DD   128
#define GG   64
#define LL   4
#define NCLS 10
#define ET   (EE + NN)
#define BNEPS 1e-5f

// ---------------- scratch (__device__ globals; no allocs allowed) -----------
__device__ float  d_h[NN * DD];        // node features (running h)
__device__ uint2  d_mh[NN * 32];       // m_scaled = dinv*h@W, fp16
__device__ float  d_agg[NN * DD];      // aggregated messages (+bias), fp32
__device__ int    d_counts[NN];
__device__ int    d_offs[NN + 1];
__device__ int    d_cursor[NN];
__device__ float  d_dinv[NN];
__device__ int    d_ssrc[ET];
__device__ float  d_stats[LL * 2 * DD];  // per-layer [sum | sumsq], zeroed in k_prep
__device__ int    d_gcnt[GG];
__device__ int    d_is64;
__device__ __half d_wth[LL * DD * DD]; // fp16 transposed layer weights [l][n][k]
__device__ __half d_wtph[DD * 160];    // fp16 transposed+padded emb weights

// ---------------- index dtype handling --------------------------------------
__device__ __forceinline__ int ld_idx(const void* p, long long i, int is64) {
    return is64 ? (int)((const long long*)p)[i] : ((const int*)p)[i];
}

// ---------------- prep: dtype detect + weight transpose/convert + zeroing ----
__global__ void k_prep(const float* __restrict__ W_emb,
                       const float* __restrict__ W_gcn, const void* ei) {
    int idx = blockIdx.x * blockDim.x + threadIdx.x;
    if (idx == 0) {
        const long long* p = (const long long*)ei;
        int is64 = 1;
        for (int i = 0; i < 8; i++) {
            long long v = p[i];
            if (v < 0 || v >= NN) is64 = 0;
        }
        d_is64 = is64;
    }
    if (idx < NN) d_counts[idx] = 0;
    if (idx < GG) d_gcnt[idx] = 0;
    if (idx < LL * 2 * DD) d_stats[idx] = 0.f;
    if (idx < DD * 160) {
        int n = idx / 160, k = idx % 160;
        d_wtph[idx] = __float2half((k < DINF) ? W_emb[k * DD + n] : 0.f);
    } else if (idx < DD * 160 + LL * DD * DD) {
        int r2 = idx - DD * 160;
        int l = r2 / (DD * DD), r = r2 % (DD * DD);
        int n = r / DD, k = r % DD;
        d_wth[r2] = __float2half(W_gcn[l * DD * DD + k * DD + n]);
    }
}

// ---------------- hist: edge in-degree + batch histogram ---------------------
__global__ void k_hist(const void* ei, const void* batch) {
    int i = blockIdx.x * blockDim.x + threadIdx.x;
    int is64 = d_is64;
    if (i < EE) {
        atomicAdd(&d_counts[ld_idx(ei, (long long)EE + i, is64)], 1);
    } else if (i < EE + NN) {
        atomicAdd(&d_gcnt[ld_idx(batch, i - EE, is64)], 1);
    }
}

// ---------------- scan: offsets + dinv + cursor zero -------------------------
__global__ void k_scan() {
    __shared__ int s[1024];
    const int T = 1024;
    int t = threadIdx.x;
    const int chunk = (NN + T - 1) / T;
    int beg = t * chunk;
    int end = min(beg + chunk, NN);
    int sum = 0;
    for (int i = beg; i < end; i++) {
        int deg = d_counts[i] + 1;           // + self loop
        sum += deg;
        d_dinv[i] = rsqrtf((float)deg);
        d_cursor[i] = 0;
    }
    s[t] = sum;
    __syncthreads();
    for (int off = 1; off < T; off <<= 1) {
        int v = (t >= off) ? s[t - off] : 0;
        __syncthreads();
        s[t] += v;
        __syncthreads();
    }
    int run = (t == 0) ? 0 : s[t - 1];
    for (int i = beg; i < end; i++) { d_offs[i] = run; run += d_counts[i] + 1; }
    if (t == T - 1) d_offs[NN] = run;
}

__global__ void k_scatter(const void* ei) {
    long long e = (long long)blockIdx.x * blockDim.x + threadIdx.x;
    int is64 = d_is64;
    if (e < EE) {
        int s = ld_idx(ei, e, is64);
        int d = ld_idx(ei, (long long)EE + e, is64);
        int p = d_offs[d] + atomicAdd(&d_cursor[d], 1);
        d_ssrc[p] = s;
    } else if (e < ET) {
        int i = (int)(e - EE);
        int p = d_offs[i] + atomicAdd(&d_cursor[i], 1);
        d_ssrc[p] = i;
    }
}

// ================= fp16 mma.sync GEMM (m16n8k16), SINGLE STAGE ==============
// C[M,128] = A[M,K] @ Bt[128,K]^T.  CTA tile 64x128 (grid 2x finer), 8 warps,
// warp tile 16x64, FULL K resident in dynamic smem, ONE barrier.
// 3 CTAs/SM target (acc = 32 regs/thread).
// FUSE_BN: A-load applies h_new = h + relu(agg*scale+shift), writes h back.
// HALF_OUT: epilogue writes dinv[row]*acc as fp16 into d_mh.

__device__ __forceinline__ uint32_t pack2(float a, float b) {
    __half2 h = __floats2half2_rn(a, b);
    return *reinterpret_cast<uint32_t*>(&h);
}

__device__ __forceinline__ void mma_f16(float* d, uint32_t a0, uint32_t a1,
                                        uint32_t a2, uint32_t a3,
                                        uint32_t b0, uint32_t b1) {
    asm volatile(
        "mma.sync.aligned.m16n8k16.row.col.f32.f16.f16.f32 "
        "{%0,%1,%2,%3}, {%4,%5,%6,%7}, {%8,%9}, {%0,%1,%2,%3};"
        : "+f"(d[0]), "+f"(d[1]), "+f"(d[2]), "+f"(d[3])
        : "r"(a0), "r"(a1), "r"(a2), "r"(a3), "r"(b0), "r"(b1));
}

template<int KC, bool PADK, bool FUSE_BN, bool HALF_OUT>
__global__ __launch_bounds__(256, 3) void k_gemm_mma(
    const float* __restrict__ A, float* __restrict__ Aw,
    int lda, int kmax,
    const __half* __restrict__ Bth, int ldbh,
    const float* __restrict__ bias, float* __restrict__ Cf,
    const float* __restrict__ statsPrev,
    const float* __restrict__ gammaPrev, const float* __restrict__ betaPrev,
    const float* __restrict__ aggPrev, int M)
{
    extern __shared__ __align__(16) uint32_t smdyn[];
    uint32_t* As = smdyn;                 // KC * 1024 uint32 (64 rows)
    uint32_t* Bs = smdyn + KC * 1024;     // KC * 2048 uint32 (128 rows)
    __shared__ float s_sc[DD], s_sh[DD];

    int t = threadIdx.x;
    int wid = t >> 5, lane = t & 31;
    int wm = wid & 3, wn = wid >> 2;      // wm: 16-row slot, wn: 64-col slot
    int qr = lane >> 2, qc = lane & 3;
    int m0 = blockIdx.x * 64;

    if (FUSE_BN) {
        if (t < DD) {
            float mu = statsPrev[t] * (1.f / NN);
            float var = statsPrev[DD + t] * (1.f / NN) - mu * mu;
            float sc = gammaPrev[t] * rsqrtf(var + BNEPS);
            s_sc[t] = sc;
            s_sh[t] = betaPrev[t] - mu * sc;
        }
        __syncthreads();
    }

    // ---- A load: 64 rows x (KC*4) vec8-slots = KC iterations ----
#pragma unroll
    for (int s = 0; s < KC; s++) {
        int slot = t + s * 256;
        int r = slot / (KC * 4);
        int cc = slot - r * (KC * 4);
        int chunk = cc >> 2, c = cc & 3;
        int grow = m0 + r;

        uint32_t pa0, pa1, pa2, pa3;
        if (PADK) {
            float f[8];
#pragma unroll
            for (int d = 0; d < 8; d++) {
                int k = cc * 8 + d;
                f[d] = (grow < M && k < kmax) ? A[(size_t)grow * lda + k] : 0.f;
            }
            pa0 = pack2(f[0], f[1]); pa1 = pack2(f[2], f[3]);
            pa2 = pack2(f[4], f[5]); pa3 = pack2(f[6], f[7]);
        } else {
            float4 v0 = make_float4(0.f, 0.f, 0.f, 0.f);
            float4 v1 = make_float4(0.f, 0.f, 0.f, 0.f);
            if (grow < M) {
                size_t off = (size_t)grow * lda + cc * 8;
                v0 = *reinterpret_cast<const float4*>(A + off);
                v1 = *reinterpret_cast<const float4*>(A + off + 4);
                if (FUSE_BN) {
                    float4 g0 = *reinterpret_cast<const float4*>(aggPrev + off);
                    float4 g1 = *reinterpret_cast<const float4*>(aggPrev + off + 4);
                    int col = cc * 8;
                    v0.x += fmaxf(0.f, g0.x * s_sc[col + 0] + s_sh[col + 0]);
                    v0.y += fmaxf(0.f, g0.y * s_sc[col + 1] + s_sh[col + 1]);
                    v0.z += fmaxf(0.f, g0.z * s_sc[col + 2] + s_sh[col + 2]);
                    v0.w += fmaxf(0.f, g0.w * s_sc[col + 3] + s_sh[col + 3]);
                    v1.x += fmaxf(0.f, g1.x * s_sc[col + 4] + s_sh[col + 4]);
                    v1.y += fmaxf(0.f, g1.y * s_sc[col + 5] + s_sh[col + 5]);
                    v1.z += fmaxf(0.f, g1.z * s_sc[col + 6] + s_sh[col + 6]);
                    v1.w += fmaxf(0.f, g1.w * s_sc[col + 7] + s_sh[col + 7]);
                    *reinterpret_cast<float4*>(Aw + off) = v0;
                    *reinterpret_cast<float4*>(Aw + off + 4) = v1;
                }
            }
            pa0 = pack2(v0.x, v0.y); pa1 = pack2(v0.z, v0.w);
            pa2 = pack2(v1.x, v1.y); pa3 = pack2(v1.z, v1.w);
        }
        uint32_t* dstA = &As[chunk * 1024 + r * 16 + c];
        dstA[0] = pa0; dstA[4] = pa1; dstA[8] = pa2; dstA[12] = pa3;
    }
    // ---- B load: 128 rows x (KC*4) slots = 2*KC iterations ----
#pragma unroll
    for (int s = 0; s < 2 * KC; s++) {
        int slot = t + s * 256;
        int r = slot / (KC * 4);
        int cc = slot - r * (KC * 4);
        int chunk = cc >> 2, c = cc & 3;
        uint4 wb = *reinterpret_cast<const uint4*>(Bth + (size_t)r * ldbh + cc * 8);
        uint32_t* dstB = &Bs[chunk * 2048 + r * 16 + c];
        dstB[0] = wb.x; dstB[4] = wb.y; dstB[8] = wb.z; dstB[12] = wb.w;
    }
    __syncthreads();

    // ---- compute: KC chunks, no further barriers ----
    float acc[8][4];
#pragma unroll
    for (int ni = 0; ni < 8; ni++)
#pragma unroll
        for (int j = 0; j < 4; j++) acc[ni][j] = 0.f;

    const uint4* As4 = reinterpret_cast<const uint4*>(As);
    const uint4* Bs4 = reinterpret_cast<const uint4*>(Bs);
#pragma unroll
    for (int chunk = 0; chunk < KC; chunk++) {
        const uint4* Ac = As4 + chunk * 256;
        const uint4* Bc = Bs4 + chunk * 512;
        uint4 af[2];
#pragma unroll
        for (int h = 0; h < 2; h++) {
            int row = wm * 16 + h * 8 + qr;
            af[h] = Ac[row * 4 + qc];
        }
#pragma unroll
        for (int ni = 0; ni < 8; ni++) {
            int row = wn * 64 + ni * 8 + qr;
            uint4 bf = Bc[row * 4 + qc];
            mma_f16(acc[ni], af[0].x, af[1].x, af[0].y, af[1].y, bf.x, bf.y);
            mma_f16(acc[ni], af[0].z, af[1].z, af[0].w, af[1].w, bf.z, bf.w);
        }
    }

    // ---- epilogue ----
    int r0 = m0 + wm * 16 + qr;
    int r1 = r0 + 8;
    if (HALF_OUT) {
        float dv0 = (r0 < M) ? d_dinv[r0] : 0.f;
        float dv1 = (r1 < M) ? d_dinv[r1] : 0.f;
        __half2* mh2 = reinterpret_cast<__half2*>(d_mh);
#pragma unroll
        for (int ni = 0; ni < 8; ni++) {
            int col = wn * 64 + ni * 8 + qc * 2;
            if (r0 < M)
                mh2[(size_t)r0 * 64 + (col >> 1)] =
                    __floats2half2_rn(acc[ni][0] * dv0, acc[ni][1] * dv0);
            if (r1 < M)
                mh2[(size_t)r1 * 64 + (col >> 1)] =
                    __floats2half2_rn(acc[ni][2] * dv1, acc[ni][3] * dv1);
        }
    } else {
#pragma unroll
        for (int ni = 0; ni < 8; ni++) {
            int col = wn * 64 + ni * 8 + qc * 2;
            float b0 = 0.f, b1 = 0.f;
            if (bias) { b0 = bias[col]; b1 = bias[col + 1]; }
            if (r0 < M) {
                float2 o = make_float2(acc[ni][0] + b0, acc[ni][1] + b1);
                *reinterpret_cast<float2*>(Cf + (size_t)r0 * DD + col) = o;
            }
            if (r1 < M) {
                float2 o = make_float2(acc[ni][2] + b0, acc[ni][3] + b1);
                *reinterpret_cast<float2*>(Cf + (size_t)r1 * DD + col) = o;
            }
        }
    }
}

// ---------------- edge aggregation + BN stats --------------------------------
__device__ __forceinline__ void acc8(float* a, uint4 v) {
    float2 p0 = __half22float2(*reinterpret_cast<__half2*>(&v.x));
    float2 p1 = __half22float2(*reinterpret_cast<__half2*>(&v.y));
    float2 p2 = __half22float2(*reinterpret_cast<__half2*>(&v.z));
    float2 p3 = __half22float2(*reinterpret_cast<__half2*>(&v.w));
    a[0] += p0.x; a[1] += p0.y; a[2] += p1.x; a[3] += p1.y;
    a[4] += p2.x; a[5] += p2.y; a[6] += p3.x; a[7] += p3.y;
}

__global__ __launch_bounds__(256) void k_agg_stats(
    const float* __restrict__ bias, float* __restrict__ stats)
{
    __shared__ float psum[8][DD], psq[8][DD];
    int t = threadIdx.x;
    int wid = t >> 5, lane = t & 31;
    int half_id = lane >> 4, sub = lane & 15;
    int node = blockIdx.x * 8 + wid;     // NN = 50000 = 6250*8

    int e0 = d_offs[node], e1 = d_offs[node + 1];
    const uint4* mh4 = reinterpret_cast<const uint4*>(d_mh);

    float a[8];
#pragma unroll
    for (int j = 0; j < 8; j++) a[j] = 0.f;

    int e = e0 + half_id;
    for (; e + 6 < e1; e += 8) {
        int s0 = d_ssrc[e],     s1 = d_ssrc[e + 2];
        int s2 = d_ssrc[e + 4], s3 = d_ssrc[e + 6];
        uint4 v0 = mh4[(size_t)s0 * 16 + sub];
        uint4 v1 = mh4[(size_t)s1 * 16 + sub];
        uint4 v2 = mh4[(size_t)s2 * 16 + sub];
        uint4 v3 = mh4[(size_t)s3 * 16 + sub];
        acc8(a, v0); acc8(a, v1); acc8(a, v2); acc8(a, v3);
    }
    for (; e < e1; e += 2) {
        uint4 v = mh4[(size_t)d_ssrc[e] * 16 + sub];
        acc8(a, v);
    }
    __syncwarp();
#pragma unroll
    for (int j = 0; j < 8; j++)
        a[j] += __shfl_down_sync(0xffffffffu, a[j], 16);

    if (half_id == 0) {
        float dv = d_dinv[node];
        const float4* b4 = reinterpret_cast<const float4*>(bias);
        float4 b0 = b4[sub * 2], b1 = b4[sub * 2 + 1];
        float4 o0 = make_float4(a[0] * dv + b0.x, a[1] * dv + b0.y,
                                a[2] * dv + b0.z, a[3] * dv + b0.w);
        float4 o1 = make_float4(a[4] * dv + b1.x, a[5] * dv + b1.y,
                                a[6] * dv + b1.z, a[7] * dv + b1.w);
        float4* out4 = reinterpret_cast<float4*>(d_agg) + (size_t)node * 32;
        out4[sub * 2] = o0;
        out4[sub * 2 + 1] = o1;
        float4* ps = reinterpret_cast<float4*>(&psum[wid][0]);
        float4* pq = reinterpret_cast<float4*>(&psq[wid][0]);
        ps[sub * 2] = o0;
        ps[sub * 2 + 1] = o1;
        pq[sub * 2] = make_float4(o0.x * o0.x, o0.y * o0.y, o0.z * o0.z, o0.w * o0.w);
        pq[sub * 2 + 1] = make_float4(o1.x * o1.x, o1.y * o1.y, o1.z * o1.z, o1.w * o1.w);
    }
    __syncthreads();

    if (t < DD) {
        float s = psum[0][t] + psum[1][t] + psum[2][t] + psum[3][t]
                + psum[4][t] + psum[5][t] + psum[6][t] + psum[7][t];
        atomicAdd(&stats[t], s);
    } else {
        int c = t - DD;
        float q = psq[0][c] + psq[1][c] + psq[2][c] + psq[3][c]
                + psq[4][c] + psq[5][c] + psq[6][c] + psq[7][c];
        atomicAdd(&stats[DD + c], q);
    }
}

// ---------------- fused BN3 + mean-pool + MLP readout -------------------------
__global__ __launch_bounds__(256) void k_pool_mlp(
    const float* __restrict__ gamma, const float* __restrict__ beta,
    const float* __restrict__ W1, const float* __restrict__ b1,
    const float* __restrict__ W2, const float* __restrict__ b2,
    const float* __restrict__ W3, const float* __restrict__ b3,
    float* __restrict__ out)
{
    __shared__ float sc[DD], sh[DD], hg[DD], z1[64], z2[32], part[2][DD];
    __shared__ int sst;
    int g = blockIdx.x, t = threadIdx.x;
    int tt = t & 127, half = t >> 7;

    if (t < DD) {
        const float* st = d_stats + 3 * 2 * DD;
        float mu = st[t] * (1.f / NN);
        float var = st[DD + t] * (1.f / NN) - mu * mu;
        float s = gamma[t] * rsqrtf(var + BNEPS);
        sc[t] = s;
        sh[t] = beta[t] - mu * s;
    }
    if (t == 0) {
        int run = 0;
        for (int i = 0; i < g; i++) run += d_gcnt[i];
        sst = run;
    }
    __syncthreads();

    int s0 = sst, c = d_gcnt[g];
    float acc = 0.f;
    for (int r = half; r < c; r += 2) {
        size_t off = (size_t)(s0 + r) * DD + tt;
        acc += d_h[off] + fmaxf(0.f, d_agg[off] * sc[tt] + sh[tt]);
    }
    part[half][tt] = acc;
    __syncthreads();
    if (t < DD) hg[t] = (part[0][t] + part[1][t]) / fmaxf((float)c, 1.f);
    __syncthreads();

    if (t < 64) {
        float a = b1[t];
        for (int k = 0; k < DD; k++) a = fmaf(hg[k], W1[k * 64 + t], a);
        z1[t] = fmaxf(0.f, a);
    }
    __syncthreads();
    if (t < 32) {
        float a = b2[t];
        for (int k = 0; k < 64; k++) a = fmaf(z1[k], W2[k * 32 + t], a);
        z2[t] = fmaxf(0.f, a);
    }
    __syncthreads();
    if (t < NCLS) {
        float a = b3[t];
        for (int k = 0; k < 32; k++) a = fmaf(z2[k], W3[k * NCLS + t], a);
        out[g * NCLS + t] = a;
    }
}

// ---------------- launch ------------------------------------------------------
extern "C" void kernel_launch(void* const* d_in, const int* in_sizes, int n_in,
                              void* d_out, int out_size) {
    const float* x        = (const float*)d_in[0];
    const void*  ei       = d_in[1];
    const void*  batch    = d_in[2];
    const float* W_emb    = (const float*)d_in[3];
    const float* b_emb    = (const float*)d_in[4];
    const float* W_gcn    = (const float*)d_in[5];
    const float* b_gcn    = (const float*)d_in[6];
    const float* bn_gamma = (const float*)d_in[7];
    const float* bn_beta  = (const float*)d_in[8];
    const float* W_r1     = (const float*)d_in[9];
    const float* b_r1     = (const float*)d_in[10];
    const float* W_r2     = (const float*)d_in[11];
    const float* b_r2     = (const float*)d_in[12];
    const float* W_r3     = (const float*)d_in[13];
    const float* b_r3     = (const float*)d_in[14];
    float* out = (float*)d_out;

    float*  p_h;     cudaGetSymbolAddress((void**)&p_h, d_h);
    float*  p_agg;   cudaGetSymbolAddress((void**)&p_agg, d_agg);
    float*  p_stats; cudaGetSymbolAddress((void**)&p_stats, d_stats);
    __half* p_wth;   cudaGetSymbolAddress((void**)&p_wth, d_wth);
    __half* p_wtph;  cudaGetSymbolAddress((void**)&p_wtph, d_wtph);

    const int NBLK = (NN + 63) / 64;     // 782
    const int PREP = DD * 160 + LL * DD * DD;
    const int SM4 = (4 * 1024 + 4 * 2048) * 4;   // 49152 B
    const int SM5 = (5 * 1024 + 5 * 2048) * 4;   // 61440 B

    static bool attr_done = false;
    if (!attr_done) {
        cudaFuncSetAttribute(k_gemm_mma<5, true, false, false>,
                             cudaFuncAttributeMaxDynamicSharedMemorySize, SM5);
        cudaFuncSetAttribute(k_gemm_mma<4, false, false, true>,
                             cudaFuncAttributeMaxDynamicSharedMemorySize, SM4);
        cudaFuncSetAttribute(k_gemm_mma<4, false, true, true>,
                             cudaFuncAttributeMaxDynamicSharedMemorySize, SM4);
        attr_done = true;
    }

    // --- preprocessing (also zeroes counts / gcnt / stats) ---
    k_prep<<<(PREP + 255) / 256, 256>>>(W_emb, W_gcn, ei);
    k_hist<<<(EE + NN + 255) / 256, 256>>>(ei, batch);
    k_scan<<<1, 1024>>>();

    // --- embedding GEMM (profile slot 5) ---
    k_gemm_mma<5, true, false, false><<<NBLK, 256, SM5>>>(
        x, nullptr, DINF, DINF, p_wtph, 160, b_emb, p_h,
        nullptr, nullptr, nullptr, nullptr, NN);

    // --- layer 0 GEMM: m = dinv * (h0 @ W0) ---
    k_gemm_mma<4, false, false, true><<<NBLK, 256, SM4>>>(
        p_h, nullptr, DD, DD, p_wth, DD, nullptr, nullptr,
        nullptr, nullptr, nullptr, nullptr, NN);

    // --- CSR scatter (must precede first aggregation) ---
    k_scatter<<<(ET + 255) / 256, 256>>>(ei);

    k_agg_stats<<<NN / 8, 256>>>(b_gcn, p_stats);

    // --- layers 1..3: BN_{l-1}+relu+residual fused into A-load ---
    for (int l = 1; l < LL; l++) {
        k_gemm_mma<4, false, true, true><<<NBLK, 256, SM4>>>(
            p_h, p_h, DD, DD, p_wth + l * DD * DD, DD, nullptr, nullptr,
            p_stats + (l - 1) * 2 * DD,
            bn_gamma + (l - 1) * DD, bn_beta + (l - 1) * DD,
            p_agg, NN);
        k_agg_stats<<<NN / 8, 256>>>(b_gcn + l * DD, p_stats + l * 2 * DD);
    }

    // --- fused BN3 + mean-pool + MLP ---
    k_pool_mlp<<<GG, 256>>>(bn_gamma + 3 * DD, bn_beta + 3 * DD,
                            W_r1, b_r1, W_r2, b_r2, W_r3, b_r3, out);
}

// round 16
// speedup vs baseline: 1.0340x; 1.0340x over previous
#include <cuda_runtime.h>
#include <cuda_fp16.h>
#include <math.h>
#include <cstdint>

#define NN   50000
#define EE   800000
#define DINF 146
#define DD   128
#define GG   64
#define LL   4
#define NCLS 10
#define ET   (EE + NN)
#define BNEPS 1e-5f

// ---------------- scratch (__device__ globals; no allocs allowed) -----------
__device__ float  d_h[NN * DD];        // node features (running h)
__device__ uint2  d_mh[NN * 32];       // m_scaled = dinv*h@W, fp16
__device__ float  d_agg[NN * DD];      // aggregated messages (+bias), fp32
__device__ int    d_counts[NN];
__device__ int    d_offs[NN + 1];
__device__ int    d_cursor[NN];
__device__ float  d_dinv[NN];
__device__ int    d_ssrc[ET];
__device__ float  d_stats[LL * 2 * DD];  // per-layer [sum | sumsq], zeroed in k_prep
__device__ int    d_gcnt[GG];
__device__ int    d_is64;
__device__ __half d_wth[LL * DD * DD]; // fp16 transposed layer weights [l][n][k]
__device__ __half d_wtph[DD * 160];    // fp16 transposed+padded emb weights

// ---------------- index dtype handling --------------------------------------
__device__ __forceinline__ int ld_idx(const void* p, long long i, int is64) {
    return is64 ? (int)((const long long*)p)[i] : ((const int*)p)[i];
}

// ---------------- prep: dtype detect + weight transpose/convert + zeroing ----
__global__ void k_prep(const float* __restrict__ W_emb,
                       const float* __restrict__ W_gcn, const void* ei) {
    int idx = blockIdx.x * blockDim.x + threadIdx.x;
    if (idx == 0) {
        const long long* p = (const long long*)ei;
        int is64 = 1;
        for (int i = 0; i < 8; i++) {
            long long v = p[i];
            if (v < 0 || v >= NN) is64 = 0;
        }
        d_is64 = is64;
    }
    if (idx < NN) d_counts[idx] = 0;
    if (idx < GG) d_gcnt[idx] = 0;
    if (idx < LL * 2 * DD) d_stats[idx] = 0.f;
    if (idx < DD * 160) {
        int n = idx / 160, k = idx % 160;
        d_wtph[idx] = __float2half((k < DINF) ? W_emb[k * DD + n] : 0.f);
    } else if (idx < DD * 160 + LL * DD * DD) {
        int r2 = idx - DD * 160;
        int l = r2 / (DD * DD), r = r2 % (DD * DD);
        int n = r / DD, k = r % DD;
        d_wth[r2] = __float2half(W_gcn[l * DD * DD + k * DD + n]);
    }
}

// ---------------- hist: edge in-degree + batch histogram ---------------------
__global__ void k_hist(const void* ei, const void* batch) {
    int i = blockIdx.x * blockDim.x + threadIdx.x;
    int is64 = d_is64;
    if (i < EE) {
        atomicAdd(&d_counts[ld_idx(ei, (long long)EE + i, is64)], 1);
    } else if (i < EE + NN) {
        atomicAdd(&d_gcnt[ld_idx(batch, i - EE, is64)], 1);
    }
}

// ---------------- scan: offsets + dinv + cursor zero -------------------------
__global__ void k_scan() {
    __shared__ int s[1024];
    const int T = 1024;
    int t = threadIdx.x;
    const int chunk = (NN + T - 1) / T;
    int beg = t * chunk;
    int end = min(beg + chunk, NN);
    int sum = 0;
    for (int i = beg; i < end; i++) {
        int deg = d_counts[i] + 1;           // + self loop
        sum += deg;
        d_dinv[i] = rsqrtf((float)deg);
        d_cursor[i] = 0;
    }
    s[t] = sum;
    __syncthreads();
    for (int off = 1; off < T; off <<= 1) {
        int v = (t >= off) ? s[t - off] : 0;
        __syncthreads();
        s[t] += v;
        __syncthreads();
    }
    int run = (t == 0) ? 0 : s[t - 1];
    for (int i = beg; i < end; i++) { d_offs[i] = run; run += d_counts[i] + 1; }
    if (t == T - 1) d_offs[NN] = run;
}

__global__ void k_scatter(const void* ei) {
    long long e = (long long)blockIdx.x * blockDim.x + threadIdx.x;
    int is64 = d_is64;
    if (e < EE) {
        int s = ld_idx(ei, e, is64);
        int d = ld_idx(ei, (long long)EE + e, is64);
        int p = d_offs[d] + atomicAdd(&d_cursor[d], 1);
        d_ssrc[p] = s;
    } else if (e < ET) {
        int i = (int)(e - EE);
        int p = d_offs[i] + atomicAdd(&d_cursor[i], 1);
        d_ssrc[p] = i;
    }
}

// ============ fp16 mma.sync GEMM (m16n8k16) + ldmatrix, SINGLE STAGE ========
// C[M,128] = A[M,K] @ Bt[128,K]^T.  CTA tile 128x128, 8 warps (32x64 warp
// tile).  Smem: C chunks of k64, natural K-major 128B rows, 16B-slot swizzle
// s^=(r&7): STS.128 fills and ldmatrix reads both bank-conflict-free.
// FUSE_BN: A-load applies h_new = h + relu(agg*scale+shift), writes h back.
// HALF_OUT: epilogue writes dinv[row]*acc as fp16 into d_mh.

__device__ __forceinline__ uint32_t pack2(float a, float b) {
    __half2 h = __floats2half2_rn(a, b);
    return *reinterpret_cast<uint32_t*>(&h);
}

__device__ __forceinline__ void mma_f16(float* d, uint32_t a0, uint32_t a1,
                                        uint32_t a2, uint32_t a3,
                                        uint32_t b0, uint32_t b1) {
    asm volatile(
        "mma.sync.aligned.m16n8k16.row.col.f32.f16.f16.f32 "
        "{%0,%1,%2,%3}, {%4,%5,%6,%7}, {%8,%9}, {%0,%1,%2,%3};"
        : "+f"(d[0]), "+f"(d[1]), "+f"(d[2]), "+f"(d[3])
        : "r"(a0), "r"(a1), "r"(a2), "r"(a3), "r"(b0), "r"(b1));
}

__device__ __forceinline__ void ldsm_x4(uint32_t* r, uint32_t addr) {
    asm volatile(
        "ldmatrix.sync.aligned.m8n8.x4.shared.b16 {%0,%1,%2,%3}, [%4];"
        : "=r"(r[0]), "=r"(r[1]), "=r"(r[2]), "=r"(r[3]) : "r"(addr));
}

template<int C, bool PADK, bool FUSE_BN, bool HALF_OUT>
__global__ __launch_bounds__(256, 2) void k_gemm_mma(
    const float* __restrict__ A, float* __restrict__ Aw,
    int lda, int kmax,
    const __half* __restrict__ Bth, int ldbh,
    const float* __restrict__ bias, float* __restrict__ Cf,
    const float* __restrict__ statsPrev,
    const float* __restrict__ gammaPrev, const float* __restrict__ betaPrev,
    const float* __restrict__ aggPrev, int M)
{
    extern __shared__ __align__(16) char smraw[];
    uint32_t sbase = (uint32_t)__cvta_generic_to_shared(smraw);
    uint32_t aBase = sbase;
    uint32_t bBase = sbase + C * 16384;
    __shared__ float s_sc[DD], s_sh[DD];

    int t = threadIdx.x;
    int wid = t >> 5, lane = t & 31;
    int wm = wid & 3, wn = wid >> 2;
    int qr = lane >> 2, qc = lane & 3;
    int m0 = blockIdx.x * 128;

    if (FUSE_BN) {
        if (t < DD) {
            float mu = statsPrev[t] * (1.f / NN);
            float var = statsPrev[DD + t] * (1.f / NN) - mu * mu;
            float sc = gammaPrev[t] * rsqrtf(var + BNEPS);
            s_sc[t] = sc;
            s_sh[t] = betaPrev[t] - mu * sc;
        }
        __syncthreads();
    }

    // ---- A fill: C*4 iterations, one STS.128 each (conflict-free) ----
#pragma unroll
    for (int i = 0; i < C * 4; i++) {
        int linear = i * 256 + t;           // over C*1024 slots
        int chunk = linear >> 10;
        int rs = linear & 1023;
        int r = rs >> 3, s = rs & 7;
        int grow = m0 + r;
        int k0 = chunk * 64 + s * 8;

        uint32_t p0, p1, p2, p3;
        if (PADK) {
            float f[8];
#pragma unroll
            for (int d = 0; d < 8; d++)
                f[d] = (grow < M && k0 + d < kmax) ? A[(size_t)grow * lda + k0 + d] : 0.f;
            p0 = pack2(f[0], f[1]); p1 = pack2(f[2], f[3]);
            p2 = pack2(f[4], f[5]); p3 = pack2(f[6], f[7]);
        } else {
            float4 v0 = make_float4(0.f, 0.f, 0.f, 0.f);
            float4 v1 = make_float4(0.f, 0.f, 0.f, 0.f);
            if (grow < M) {
                size_t off = (size_t)grow * lda + k0;
                v0 = *reinterpret_cast<const float4*>(A + off);
                v1 = *reinterpret_cast<const float4*>(A + off + 4);
                if (FUSE_BN) {
                    float4 g0 = *reinterpret_cast<const float4*>(aggPrev + off);
                    float4 g1 = *reinterpret_cast<const float4*>(aggPrev + off + 4);
                    v0.x += fmaxf(0.f, g0.x * s_sc[k0 + 0] + s_sh[k0 + 0]);
                    v0.y += fmaxf(0.f, g0.y * s_sc[k0 + 1] + s_sh[k0 + 1]);
                    v0.z += fmaxf(0.f, g0.z * s_sc[k0 + 2] + s_sh[k0 + 2]);
                    v0.w += fmaxf(0.f, g0.w * s_sc[k0 + 3] + s_sh[k0 + 3]);
                    v1.x += fmaxf(0.f, g1.x * s_sc[k0 + 4] + s_sh[k0 + 4]);
                    v1.y += fmaxf(0.f, g1.y * s_sc[k0 + 5] + s_sh[k0 + 5]);
                    v1.z += fmaxf(0.f, g1.z * s_sc[k0 + 6] + s_sh[k0 + 6]);
                    v1.w += fmaxf(0.f, g1.w * s_sc[k0 + 7] + s_sh[k0 + 7]);
                    *reinterpret_cast<float4*>(Aw + off) = v0;
                    *reinterpret_cast<float4*>(Aw + off + 4) = v1;
                }
            }
            p0 = pack2(v0.x, v0.y); p1 = pack2(v0.z, v0.w);
            p2 = pack2(v1.x, v1.y); p3 = pack2(v1.z, v1.w);
        }
        uint32_t addr = aBase + chunk * 16384 + r * 128 + ((s ^ (r & 7)) << 4);
        asm volatile("st.shared.v4.b32 [%0], {%1,%2,%3,%4};"
                     :: "r"(addr), "r"(p0), "r"(p1), "r"(p2), "r"(p3));
    }
    // ---- B fill: C*4 iterations ----
#pragma unroll
    for (int i = 0; i < C * 4; i++) {
        int linear = i * 256 + t;
        int chunk = linear >> 10;
        int rs = linear & 1023;
        int r = rs >> 3, s = rs & 7;
        int k0 = chunk * 64 + s * 8;
        uint4 wb = make_uint4(0u, 0u, 0u, 0u);
        if (k0 < ldbh)
            wb = *reinterpret_cast<const uint4*>(Bth + (size_t)r * ldbh + k0);
        uint32_t addr = bBase + chunk * 16384 + r * 128 + ((s ^ (r & 7)) << 4);
        asm volatile("st.shared.v4.b32 [%0], {%1,%2,%3,%4};"
                     :: "r"(addr), "r"(wb.x), "r"(wb.y), "r"(wb.z), "r"(wb.w));
    }
    __syncthreads();

    // ---- compute ----
    float acc[2][8][4];
#pragma unroll
    for (int mi = 0; mi < 2; mi++)
#pragma unroll
        for (int ni = 0; ni < 8; ni++)
#pragma unroll
            for (int j = 0; j < 4; j++) acc[mi][ni][j] = 0.f;

    int g01 = (lane >> 3) & 1;   // 0/1 within 16-lane half
    int g16 = lane >> 4;         // 0/1 half select
    int lr = lane & 7;

#pragma unroll
    for (int chunk = 0; chunk < C; chunk++) {
        uint32_t aCh = aBase + chunk * 16384;
        uint32_t bCh = bBase + chunk * 16384;
#pragma unroll
        for (int j = 0; j < 4; j++) {   // k16 steps within k64 chunk
            uint32_t af[2][4];
#pragma unroll
            for (int mi = 0; mi < 2; mi++) {
                int row = wm * 32 + mi * 16 + g01 * 8 + lr;
                int slot = 2 * j + g16;
                ldsm_x4(af[mi], aCh + row * 128 + ((slot ^ (row & 7)) << 4));
            }
#pragma unroll
            for (int p = 0; p < 4; p++) {
                int row = wn * 64 + (2 * p + g16) * 8 + lr;
                int slot = 2 * j + g01;
                uint32_t bb[4];
                ldsm_x4(bb, bCh + row * 128 + ((slot ^ (row & 7)) << 4));
#pragma unroll
                for (int mi = 0; mi < 2; mi++) {
                    mma_f16(acc[mi][2 * p],     af[mi][0], af[mi][1],
                            af[mi][2], af[mi][3], bb[0], bb[1]);
                    mma_f16(acc[mi][2 * p + 1], af[mi][0], af[mi][1],
                            af[mi][2], af[mi][3], bb[2], bb[3]);
                }
            }
        }
    }

    // ---- epilogue ----
#pragma unroll
    for (int mi = 0; mi < 2; mi++) {
        int r0 = m0 + wm * 32 + mi * 16 + qr;
        int r1 = r0 + 8;
        if (HALF_OUT) {
            float dv0 = (r0 < M) ? d_dinv[r0] : 0.f;
            float dv1 = (r1 < M) ? d_dinv[r1] : 0.f;
            __half2* mh2 = reinterpret_cast<__half2*>(d_mh);
#pragma unroll
            for (int ni = 0; ni < 8; ni++) {
                int col = wn * 64 + ni * 8 + qc * 2;
                if (r0 < M)
                    mh2[(size_t)r0 * 64 + (col >> 1)] =
                        __floats2half2_rn(acc[mi][ni][0] * dv0, acc[mi][ni][1] * dv0);
                if (r1 < M)
                    mh2[(size_t)r1 * 64 + (col >> 1)] =
                        __floats2half2_rn(acc[mi][ni][2] * dv1, acc[mi][ni][3] * dv1);
            }
        } else {
#pragma unroll
            for (int ni = 0; ni < 8; ni++) {
                int col = wn * 64 + ni * 8 + qc * 2;
                float b0 = 0.f, b1 = 0.f;
                if (bias) { b0 = bias[col]; b1 = bias[col + 1]; }
                if (r0 < M) {
                    float2 o = make_float2(acc[mi][ni][0] + b0, acc[mi][ni][1] + b1);
                    *reinterpret_cast<float2*>(Cf + (size_t)r0 * DD + col) = o;
                }
                if (r1 < M) {
                    float2 o = make_float2(acc[mi][ni][2] + b0, acc[mi][ni][3] + b1);
                    *reinterpret_cast<float2*>(Cf + (size_t)r1 * DD + col) = o;
                }
            }
        }
    }
}

// ---------------- edge aggregation + BN stats --------------------------------
__device__ __forceinline__ void acc8(float* a, uint4 v) {
    float2 p0 = __half22float2(*reinterpret_cast<__half2*>(&v.x));
    float2 p1 = __half22float2(*reinterpret_cast<__half2*>(&v.y));
    float2 p2 = __half22float2(*reinterpret_cast<__half2*>(&v.z));
    float2 p3 = __half22float2(*reinterpret_cast<__half2*>(&v.w));
    a[0] += p0.x; a[1] += p0.y; a[2] += p1.x; a[3] += p1.y;
    a[4] += p2.x; a[5] += p2.y; a[6] += p3.x; a[7] += p3.y;
}

__global__ __launch_bounds__(256) void k_agg_stats(
    const float* __restrict__ bias, float* __restrict__ stats)
{
    __shared__ float psum[8][DD], psq[8][DD];
    int t = threadIdx.x;
    int wid = t >> 5, lane = t & 31;
    int half_id = lane >> 4, sub = lane & 15;
    int node = blockIdx.x * 8 + wid;     // NN = 50000 = 6250*8

    int e0 = d_offs[node], e1 = d_offs[node + 1];
    const uint4* mh4 = reinterpret_cast<const uint4*>(d_mh);

    float a[8];
#pragma unroll
    for (int j = 0; j < 8; j++) a[j] = 0.f;

    int e = e0 + half_id;
    for (; e + 6 < e1; e += 8) {
        int s0 = d_ssrc[e],     s1 = d_ssrc[e + 2];
        int s2 = d_ssrc[e + 4], s3 = d_ssrc[e + 6];
        uint4 v0 = mh4[(size_t)s0 * 16 + sub];
        uint4 v1 = mh4[(size_t)s1 * 16 + sub];
        uint4 v2 = mh4[(size_t)s2 * 16 + sub];
        uint4 v3 = mh4[(size_t)s3 * 16 + sub];
        acc8(a, v0); acc8(a, v1); acc8(a, v2); acc8(a, v3);
    }
    for (; e < e1; e += 2) {
        uint4 v = mh4[(size_t)d_ssrc[e] * 16 + sub];
        acc8(a, v);
    }
    __syncwarp();
#pragma unroll
    for (int j = 0; j < 8; j++)
        a[j] += __shfl_down_sync(0xffffffffu, a[j], 16);

    if (half_id == 0) {
        float dv = d_dinv[node];
        const float4* b4 = reinterpret_cast<const float4*>(bias);
        float4 b0 = b4[sub * 2], b1 = b4[sub * 2 + 1];
        float4 o0 = make_float4(a[0] * dv + b0.x, a[1] * dv + b0.y,
                                a[2] * dv + b0.z, a[3] * dv + b0.w);
        float4 o1 = make_float4(a[4] * dv + b1.x, a[5] * dv + b1.y,
                                a[6] * dv + b1.z, a[7] * dv + b1.w);
        float4* out4 = reinterpret_cast<float4*>(d_agg) + (size_t)node * 32;
        out4[sub * 2] = o0;
        out4[sub * 2 + 1] = o1;
        float4* ps = reinterpret_cast<float4*>(&psum[wid][0]);
        float4* pq = reinterpret_cast<float4*>(&psq[wid][0]);
        ps[sub * 2] = o0;
        ps[sub * 2 + 1] = o1;
        pq[sub * 2] = make_float4(o0.x * o0.x, o0.y * o0.y, o0.z * o0.z, o0.w * o0.w);
        pq[sub * 2 + 1] = make_float4(o1.x * o1.x, o1.y * o1.y, o1.z * o1.z, o1.w * o1.w);
    }
    __syncthreads();

    if (t < DD) {
        float s = psum[0][t] + psum[1][t] + psum[2][t] + psum[3][t]
                + psum[4][t] + psum[5][t] + psum[6][t] + psum[7][t];
        atomicAdd(&stats[t], s);
    } else {
        int c = t - DD;
        float q = psq[0][c] + psq[1][c] + psq[2][c] + psq[3][c]
                + psq[4][c] + psq[5][c] + psq[6][c] + psq[7][c];
        atomicAdd(&stats[DD + c], q);
    }
}

// ---------------- fused BN3 + mean-pool + MLP readout -------------------------
__global__ __launch_bounds__(256) void k_pool_mlp(
    const float* __restrict__ gamma, const float* __restrict__ beta,
    const float* __restrict__ W1, const float* __restrict__ b1,
    const float* __restrict__ W2, const float* __restrict__ b2,
    const float* __restrict__ W3, const float* __restrict__ b3,
    float* __restrict__ out)
{
    __shared__ float sc[DD], sh[DD], hg[DD], z1[64], z2[32], part[2][DD];
    __shared__ int sst;
    int g = blockIdx.x, t = threadIdx.x;
    int tt = t & 127, half = t >> 7;

    if (t < DD) {
        const float* st = d_stats + 3 * 2 * DD;
        float mu = st[t] * (1.f / NN);
        float var = st[DD + t] * (1.f / NN) - mu * mu;
        float s = gamma[t] * rsqrtf(var + BNEPS);
        sc[t] = s;
        sh[t] = beta[t] - mu * s;
    }
    if (t == 0) {
        int run = 0;
        for (int i = 0; i < g; i++) run += d_gcnt[i];
        sst = run;
    }
    __syncthreads();

    int s0 = sst, c = d_gcnt[g];
    float acc = 0.f;
    for (int r = half; r < c; r += 2) {
        size_t off = (size_t)(s0 + r) * DD + tt;
        acc += d_h[off] + fmaxf(0.f, d_agg[off] * sc[tt] + sh[tt]);
    }
    part[half][tt] = acc;
    __syncthreads();
    if (t < DD) hg[t] = (part[0][t] + part[1][t]) / fmaxf((float)c, 1.f);
    __syncthreads();

    if (t < 64) {
        float a = b1[t];
        for (int k = 0; k < DD; k++) a = fmaf(hg[k], W1[k * 64 + t], a);
        z1[t] = fmaxf(0.f, a);
    }
    __syncthreads();
    if (t < 32) {
        float a = b2[t];
        for (int k = 0; k < 64; k++) a = fmaf(z1[k], W2[k * 32 + t], a);
        z2[t] = fmaxf(0.f, a);
    }
    __syncthreads();
    if (t < NCLS) {
        float a = b3[t];
        for (int k = 0; k < 32; k++) a = fmaf(z2[k], W3[k * NCLS + t], a);
        out[g * NCLS + t] = a;
    }
}

// ---------------- launch ------------------------------------------------------
extern "C" void kernel_launch(void* const* d_in, const int* in_sizes, int n_in,
                              void* d_out, int out_size) {
    const float* x        = (const float*)d_in[0];
    const void*  ei       = d_in[1];
    const void*  batch    = d_in[2];
    const float* W_emb    = (const float*)d_in[3];
    const float* b_emb    = (const float*)d_in[4];
    const float* W_gcn    = (const float*)d_in[5];
    const float* b_gcn    = (const float*)d_in[6];
    const float* bn_gamma = (const float*)d_in[7];
    const float* bn_beta  = (const float*)d_in[8];
    const float* W_r1     = (const float*)d_in[9];
    const float* b_r1     = (const float*)d_in[10];
    const float* W_r2     = (const float*)d_in[11];
    const float* b_r2     = (const float*)d_in[12];
    const float* W_r3     = (const float*)d_in[13];
    const float* b_r3     = (const float*)d_in[14];
    float* out = (float*)d_out;

    float*  p_h;     cudaGetSymbolAddress((void**)&p_h, d_h);
    float*  p_agg;   cudaGetSymbolAddress((void**)&p_agg, d_agg);
    float*  p_stats; cudaGetSymbolAddress((void**)&p_stats, d_stats);
    __half* p_wth;   cudaGetSymbolAddress((void**)&p_wth, d_wth);
    __half* p_wtph;  cudaGetSymbolAddress((void**)&p_wtph, d_wtph);

    const int NBLK = (NN + 127) / 128;   // 391
    const int PREP = DD * 160 + LL * DD * DD;
    const int SM2 = 2 * 2 * 16384;       // 65536 B (layers, C=2)
    const int SM3 = 3 * 2 * 16384;       // 98304 B (embedding, C=3)

    static bool attr_done = false;
    if (!attr_done) {
        cudaFuncSetAttribute(k_gemm_mma<3, true, false, false>,
                             cudaFuncAttributeMaxDynamicSharedMemorySize, SM3);
        cudaFuncSetAttribute(k_gemm_mma<2, false, false, true>,
                             cudaFuncAttributeMaxDynamicSharedMemorySize, SM2);
        cudaFuncSetAttribute(k_gemm_mma<2, false, true, true>,
                             cudaFuncAttributeMaxDynamicSharedMemorySize, SM2);
        attr_done = true;
    }

    // --- preprocessing (also zeroes counts / gcnt / stats) ---
    k_prep<<<(PREP + 255) / 256, 256>>>(W_emb, W_gcn, ei);
    k_hist<<<(EE + NN + 255) / 256, 256>>>(ei, batch);
    k_scan<<<1, 1024>>>();

    // --- embedding GEMM (profile slot 5): K padded to 192, C=3 ---
    k_gemm_mma<3, true, false, false><<<NBLK, 256, SM3>>>(
        x, nullptr, DINF, DINF, p_wtph, 160, b_emb, p_h,
        nullptr, nullptr, nullptr, nullptr, NN);

    // --- layer 0 GEMM: m = dinv * (h0 @ W0) ---
    k_gemm_mma<2, false, false, true><<<NBLK, 256, SM2>>>(
        p_h, nullptr, DD, DD, p_wth, DD, nullptr, nullptr,
        nullptr, nullptr, nullptr, nullptr, NN);

    // --- CSR scatter (must precede first aggregation) ---
    k_scatter<<<(ET + 255) / 256, 256>>>(ei);

    k_agg_stats<<<NN / 8, 256>>>(b_gcn, p_stats);

    // --- layers 1..3: BN_{l-1}+relu+residual fused into A-load ---
    for (int l = 1; l < LL; l++) {
        k_gemm_mma<2, false, true, true><<<NBLK, 256, SM2>>>(
            p_h, p_h, DD, DD, p_wth + l * DD * DD, DD, nullptr, nullptr,
            p_stats + (l - 1) * 2 * DD,
            bn_gamma + (l - 1) * DD, bn_beta + (l - 1) * DD,
            p_agg, NN);
        k_agg_stats<<<NN / 8, 256>>>(b_gcn + l * DD, p_stats + l * 2 * DD);
    }

    // --- fused BN3 + mean-pool + MLP ---
    k_pool_mlp<<<GG, 256>>>(bn_gamma + 3 * DD, bn_beta + 3 * DD,
                            W_r1, b_r1, W_r2, b_r2, W_r3, b_r3, out);
}